// round 2
// baseline (speedup 1.0000x reference)
#include <cuda_runtime.h>
#include <cstdint>

// ---------------------------------------------------------------------------
// TFN: out = ((relu(relu(F@W1+b1)@W2+b2))@W3)+b3,  F = trilinear fusion
// F[b, (ai,vi,ti)] = a[b,ai]*v[b,vi]*t[b,ti],  a=[1,audio], v=[1,video], t=[1,text]
// B=256, A+1=33, V+1=33, T+1=129, K = 1089 chunks of 129, PF=128.
//
// Strategy: split-K tf32 tensor-core GEMM. Per (ai,vi) chunk:
//   P = T(256x129) @ Wc(129x128)   (tf32 mma, fp32 accum, zeroed per chunk)
//   acc[b,p] += s[b] * P[b,p]      (fp32 FMA; s[b]=a[b,ai]*v[b,vi])
// Grid 4 N-slices x 38 K-groups = 152 CTAs (one wave on GB300).
// ---------------------------------------------------------------------------

#define CHUNKS 1089
#define GSPLIT 38
#define TSTR   132            // T smem row stride (floats): banks (4r+c) conflict-free
#define WSTR   140            // W smem row stride (floats): conflict-free B-frag loads
#define TSM_FLOATS (256*TSTR + 8)      // + zero tail for k=132..135 overread at row 255
#define WSM_FLOATS (32*WSTR)
#define SMEM_BYTES ((TSM_FLOATS + WSM_FLOATS) * 4)

__device__ float g_T[257 * TSTR];          // tf32-rounded [1|text], rows pad to 132, row 256 = 0
__device__ float g_part[GSPLIT * 256 * 128];
__device__ float g_h1[256 * 128];

__device__ __forceinline__ uint32_t f2tf32(float f) {
    uint32_t u;
    asm("cvt.rna.tf32.f32 %0, %1;" : "=r"(u) : "f"(f));
    return u;
}

// ---------------------------------------------------------------------------
__global__ void prep_T(const float* __restrict__ text) {
    int b = blockIdx.x;       // 256
    int t = threadIdx.x;      // 132
    float v;
    if (t == 0)        v = 1.0f;
    else if (t <= 128) v = text[b * 128 + (t - 1)];
    else               v = 0.0f;
    g_T[b * TSTR + t] = __uint_as_float(f2tf32(v));
}

// ---------------------------------------------------------------------------
__global__ void __launch_bounds__(256, 1)
tfn_gemm(const float* __restrict__ audio, const float* __restrict__ video,
         const float* __restrict__ W1) {
    extern __shared__ float sm[];
    float* Tsm = sm;                       // TSM_FLOATS
    float* Wsm = sm + TSM_FLOATS;          // 32 x WSTR, layout [n][k] (transposed)

    const int tid   = threadIdx.x;
    const int slice = blockIdx.x;          // 0..3 : 32-wide N slice of PF=128
    const int g     = blockIdx.y;          // 0..GSPLIT-1 : K group

    // stage T into smem (vectorized), zero the small tail
    {
        const float4* src = (const float4*)g_T;
        float4* dst = (float4*)Tsm;
        #pragma unroll 4
        for (int i = tid; i < (256 * TSTR) / 4; i += 256) dst[i] = src[i];
        if (tid < 8) Tsm[256 * TSTR + tid] = 0.0f;
    }
    // zero W pad columns k = 129..139 (loads only touch k < 129)
    for (int i = tid; i < 32 * WSTR; i += 256)
        if ((i % WSTR) >= 129) Wsm[i] = 0.0f;

    const int warp  = tid >> 5;
    const int lane  = tid & 31;
    const int grp   = lane >> 2;           // 0..7
    const int tig   = lane & 3;            // 0..3
    const int mbase = warp << 5;           // each warp owns 32 batch rows

    float acc[2][4][4];
    #pragma unroll
    for (int mt = 0; mt < 2; mt++)
        #pragma unroll
        for (int nt = 0; nt < 4; nt++)
            #pragma unroll
            for (int e = 0; e < 4; e++) acc[mt][nt][e] = 0.0f;

    __syncthreads();

    for (int c = g; c < CHUNKS; c += GSPLIT) {
        const int ai = c / 33;
        const int vi = c - ai * 33;

        // per-row scales s = a[b,ai]*v[b,vi] for the 4 row-octets of this thread
        float s[4];
        #pragma unroll
        for (int r4 = 0; r4 < 4; r4++) {
            int row  = mbase + (r4 << 3) + grp;
            float av = (ai == 0) ? 1.0f : __ldg(&audio[row * 32 + ai - 1]);
            float vv = (vi == 0) ? 1.0f : __ldg(&video[row * 32 + vi - 1]);
            s[r4] = av * vv;
        }

        // load W chunk slice (129 x 32), transpose into Wsm[n][k], tf32-round
        __syncthreads();   // previous compute done before overwriting Wsm
        const float* Wg = W1 + (size_t)c * 129 * 128 + slice * 32;
        for (int i = tid; i < 129 * 8; i += 256) {
            int k  = i >> 3;
            int j4 = (i & 7) << 2;
            float4 w = *(const float4*)(Wg + (size_t)k * 128 + j4);
            Wsm[(j4 + 0) * WSTR + k] = __uint_as_float(f2tf32(w.x));
            Wsm[(j4 + 1) * WSTR + k] = __uint_as_float(f2tf32(w.y));
            Wsm[(j4 + 2) * WSTR + k] = __uint_as_float(f2tf32(w.z));
            Wsm[(j4 + 3) * WSTR + k] = __uint_as_float(f2tf32(w.w));
        }
        __syncthreads();

        // P = T @ Wc  (tf32 mma, fp32 accum), zeroed per chunk
        float tacc[2][4][4];
        #pragma unroll
        for (int mt = 0; mt < 2; mt++)
            #pragma unroll
            for (int nt = 0; nt < 4; nt++)
                #pragma unroll
                for (int e = 0; e < 4; e++) tacc[mt][nt][e] = 0.0f;

        #pragma unroll
        for (int kt = 0; kt < 17; kt++) {
            const int k0 = kt << 3;
            uint32_t a[2][4];
            #pragma unroll
            for (int mt = 0; mt < 2; mt++) {
                const int r0 = mbase + (mt << 4) + grp;
                a[mt][0] = __float_as_uint(Tsm[r0 * TSTR + k0 + tig]);
                a[mt][1] = __float_as_uint(Tsm[(r0 + 8) * TSTR + k0 + tig]);
                a[mt][2] = __float_as_uint(Tsm[r0 * TSTR + k0 + tig + 4]);
                a[mt][3] = __float_as_uint(Tsm[(r0 + 8) * TSTR + k0 + tig + 4]);
            }
            #pragma unroll
            for (int nt = 0; nt < 4; nt++) {
                uint32_t b0 = __float_as_uint(Wsm[((nt << 3) + grp) * WSTR + k0 + tig]);
                uint32_t b1 = __float_as_uint(Wsm[((nt << 3) + grp) * WSTR + k0 + tig + 4]);
                #pragma unroll
                for (int mt = 0; mt < 2; mt++) {
                    asm volatile(
                        "mma.sync.aligned.m16n8k8.row.col.f32.tf32.tf32.f32 "
                        "{%0,%1,%2,%3}, {%4,%5,%6,%7}, {%8,%9}, {%0,%1,%2,%3};"
                        : "+f"(tacc[mt][nt][0]), "+f"(tacc[mt][nt][1]),
                          "+f"(tacc[mt][nt][2]), "+f"(tacc[mt][nt][3])
                        : "r"(a[mt][0]), "r"(a[mt][1]), "r"(a[mt][2]), "r"(a[mt][3]),
                          "r"(b0), "r"(b1));
                }
            }
        }

        // acc += s[row] * P   (fp32)
        #pragma unroll
        for (int mt = 0; mt < 2; mt++)
            #pragma unroll
            for (int nt = 0; nt < 4; nt++) {
                acc[mt][nt][0] = fmaf(s[2 * mt],     tacc[mt][nt][0], acc[mt][nt][0]);
                acc[mt][nt][1] = fmaf(s[2 * mt],     tacc[mt][nt][1], acc[mt][nt][1]);
                acc[mt][nt][2] = fmaf(s[2 * mt + 1], tacc[mt][nt][2], acc[mt][nt][2]);
                acc[mt][nt][3] = fmaf(s[2 * mt + 1], tacc[mt][nt][3], acc[mt][nt][3]);
            }
    }

    // write split-K partials (no atomics; fully overwritten each replay)
    float* part = g_part + (size_t)g * (256 * 128);
    #pragma unroll
    for (int mt = 0; mt < 2; mt++) {
        int r0 = mbase + (mt << 4) + grp;
        #pragma unroll
        for (int nt = 0; nt < 4; nt++) {
            int col = (slice << 5) + (nt << 3) + (tig << 1);
            *(float2*)&part[r0 * 128 + col]       = make_float2(acc[mt][nt][0], acc[mt][nt][1]);
            *(float2*)&part[(r0 + 8) * 128 + col] = make_float2(acc[mt][nt][2], acc[mt][nt][3]);
        }
    }
}

// ---------------------------------------------------------------------------
__global__ void reduce_bias_relu(const float* __restrict__ b1) {
    int idx = blockIdx.x * 256 + threadIdx.x;   // grid 128 -> 32768 outputs
    float sum = b1[idx & 127];
    #pragma unroll
    for (int gg = 0; gg < GSPLIT; gg++) sum += g_part[gg * 32768 + idx];
    g_h1[idx] = fmaxf(sum, 0.0f);
}

// ---------------------------------------------------------------------------
__global__ void l2l3(const float* __restrict__ W2, const float* __restrict__ b2,
                     const float* __restrict__ W3, const float* __restrict__ b3,
                     float* __restrict__ out) {
    __shared__ float row[128];
    __shared__ float red[128];
    const int b = blockIdx.x;     // 256
    const int p = threadIdx.x;    // 128

    row[p] = g_h1[b * 128 + p];
    __syncthreads();

    float sum = b2[p];
    #pragma unroll 8
    for (int k = 0; k < 128; k++) sum = fmaf(row[k], W2[k * 128 + p], sum);
    float h2 = fmaxf(sum, 0.0f);

    red[p] = h2 * W3[p];
    __syncthreads();
    #pragma unroll
    for (int sft = 64; sft > 0; sft >>= 1) {
        if (p < sft) red[p] += red[p + sft];
        __syncthreads();
    }
    if (p == 0) out[b] = red[0] + b3[0];
}

// ---------------------------------------------------------------------------
extern "C" void kernel_launch(void* const* d_in, const int* in_sizes, int n_in,
                              void* d_out, int out_size) {
    (void)in_sizes; (void)n_in; (void)out_size;
    const float* audio = (const float*)d_in[0];
    const float* video = (const float*)d_in[1];
    const float* text  = (const float*)d_in[2];
    const float* W1    = (const float*)d_in[3];
    const float* b1    = (const float*)d_in[4];
    const float* W2    = (const float*)d_in[5];
    const float* b2    = (const float*)d_in[6];
    const float* W3    = (const float*)d_in[7];
    const float* b3    = (const float*)d_in[8];
    float* out = (float*)d_out;

    cudaFuncSetAttribute(tfn_gemm, cudaFuncAttributeMaxDynamicSharedMemorySize,
                         SMEM_BYTES);

    prep_T<<<256, 132>>>(text);
    dim3 grid(4, GSPLIT);
    tfn_gemm<<<grid, 256, SMEM_BYTES>>>(audio, video, W1);
    reduce_bias_relu<<<128, 256>>>(b1);
    l2l3<<<256, 128>>>(W2, b2, W3, b3, out);
}

// round 4
// speedup vs baseline: 1.2735x; 1.2735x over previous
#include <cuda_runtime.h>
#include <cstdint>

#define CHUNKS 1089
#define GSPLIT 38
#define TSTR   132                      // T row stride (words): ldmatrix phase-conflict-free
#define TSM_FLOATS (256*TSTR + 8)       // 33800 (tail zeros for row-255 overread)
#define BSTR   36                       // B row stride (words): 4*tig+grp bank-free
#define BROWS  136
#define BBUF_FLOATS (BROWS*BSTR)        // 4896
#define SMEM_BYTES ((TSM_FLOATS + 2*BBUF_FLOATS) * 4)   // 174368

__device__ float g_T[257 * TSTR];       // tf32(RNA) [1|text], zero row 256 (bss zero)
__device__ float g_part[GSPLIT * 256 * 128];
__device__ float g_h1[256 * 128];

__device__ __forceinline__ uint32_t smem_u32(const void* p) {
    uint32_t a;
    asm("{ .reg .u64 t; cvta.to.shared.u64 t, %1; cvt.u32.u64 %0, t; }" : "=r"(a) : "l"(p));
    return a;
}
__device__ __forceinline__ uint32_t f2tf32(float f) {
    uint32_t u; asm("cvt.rna.tf32.f32 %0, %1;" : "=r"(u) : "f"(f)); return u;
}
#define CP16(dst, src) asm volatile("cp.async.cg.shared.global [%0], [%1], 16;" :: "r"(dst), "l"(src))
#define CP_COMMIT()    asm volatile("cp.async.commit_group;")

// ---------------------------------------------------------------------------
__global__ void prep_T(const float* __restrict__ text) {
    int b = blockIdx.x, t = threadIdx.x;   // 256 x 132
    float v;
    if (t == 0)        v = 1.0f;
    else if (t <= 128) v = text[b * 128 + (t - 1)];
    else               v = 0.0f;
    g_T[b * TSTR + t] = __uint_as_float(f2tf32(v));
}

// ---------------------------------------------------------------------------
__global__ void __launch_bounds__(256, 1)
tfn_gemm(const float* __restrict__ audio, const float* __restrict__ video,
         const float* __restrict__ W1) {
    extern __shared__ float sm[];
    float* Tsm = sm;
    float* B0  = sm + TSM_FLOATS;
    float* B1  = B0 + BBUF_FLOATS;

    const int tid   = threadIdx.x;
    const int slice = blockIdx.x;          // 0..3
    const int g     = blockIdx.y;          // 0..37

    const uint32_t sT  = smem_u32(Tsm);
    const uint32_t sB0 = smem_u32(B0);
    const uint32_t sB1 = smem_u32(B1);

    // zero B pad rows 129..135 (both buffers) — multiplied against A overread
    for (int i = tid; i < 2 * 7 * BSTR; i += 256) {
        int bf = i / (7 * BSTR), off = 129 * BSTR + i % (7 * BSTR);
        (bf ? B1 : B0)[off] = 0.0f;
    }

    // async stage T (full 33800 words = 8450 x 16B)
    {
        const char* src = (const char*)g_T;
        #pragma unroll
        for (int t = 0; t < 33; t++) {
            int task = tid + (t << 8);
            CP16(sT + task * 16, src + (size_t)task * 16);
        }
        if (tid < 2) CP16(sT + (8448 + tid) * 16, src + (size_t)(8448 + tid) * 16);
    }
    // async stage first W chunk, same group
    {
        const char* src = (const char*)(W1 + (size_t)g * (129 * 128) + slice * 32);
        #pragma unroll
        for (int t = 0; t < 4; t++) {
            int task = tid + (t << 8);
            int k = task >> 3, j = task & 7;
            CP16(sB0 + k * (BSTR * 4) + j * 16, src + (size_t)k * 512 + j * 16);
        }
        if (tid < 8) CP16(sB0 + 128 * (BSTR * 4) + tid * 16, src + (size_t)128 * 512 + tid * 16);
    }
    CP_COMMIT();

    const int warp = tid >> 5, lane = tid & 31;
    const int grp  = lane >> 2, tig = lane & 3;
    const int mbase = warp << 5;
    // ldmatrix lane address: row = mbase + mt*16 + (lane&15), col-block = lane>>4
    const uint32_t aBase = sT + ((uint32_t)(mbase + (lane & 15)) * TSTR + ((lane >> 4) << 2)) * 4;

    float acc[2][4][4];
    #pragma unroll
    for (int mt = 0; mt < 2; mt++)
        #pragma unroll
        for (int nt = 0; nt < 4; nt++)
            #pragma unroll
            for (int e = 0; e < 4; e++) acc[mt][nt][e] = 0.0f;

    const int nch = (CHUNKS - g + GSPLIT - 1) / GSPLIT;   // 28 or 29

    for (int i = 0; i < nch; i++) {
        const int c = g + i * GSPLIT;
        const uint32_t bb = (i & 1) ? sB1 : sB0;

        if (i + 1 < nch) {  // prefetch next chunk into other buffer
            const uint32_t nb = (i & 1) ? sB0 : sB1;
            const char* src = (const char*)(W1 + (size_t)(c + GSPLIT) * (129 * 128) + slice * 32);
            #pragma unroll
            for (int t = 0; t < 4; t++) {
                int task = tid + (t << 8);
                int k = task >> 3, j = task & 7;
                CP16(nb + k * (BSTR * 4) + j * 16, src + (size_t)k * 512 + j * 16);
            }
            if (tid < 8) CP16(nb + 128 * (BSTR * 4) + tid * 16, src + (size_t)128 * 512 + tid * 16);
            CP_COMMIT();
            asm volatile("cp.async.wait_group 1;");
        } else {
            asm volatile("cp.async.wait_group 0;");
        }
        __syncthreads();

        // s[b] = a*v, with (1+2^-11) compensating tf32 B-truncation bias
        const int ai = c / 33, vi = c - ai * 33;
        float s[4];
        #pragma unroll
        for (int r4 = 0; r4 < 4; r4++) {
            int row  = mbase + (r4 << 3) + grp;
            float av = (ai == 0) ? 1.0f : __ldg(&audio[row * 32 + ai - 1]);
            float vv = (vi == 0) ? 1.0f : __ldg(&video[row * 32 + vi - 1]);
            s[r4] = av * vv * 1.00048828125f;
        }

        float tacc[2][4][4];
        #pragma unroll
        for (int mt = 0; mt < 2; mt++)
            #pragma unroll
            for (int nt = 0; nt < 4; nt++)
                #pragma unroll
                for (int e = 0; e < 4; e++) tacc[mt][nt][e] = 0.0f;

        const float* Bf = (i & 1) ? B1 : B0;
        #pragma unroll
        for (int kt = 0; kt < 17; kt++) {
            const int k0 = kt << 3;
            uint32_t a[2][4];
            #pragma unroll
            for (int mt = 0; mt < 2; mt++) {
                uint32_t ad = aBase + (uint32_t)(mt * 16 * TSTR + k0) * 4;
                asm volatile("ldmatrix.sync.aligned.m8n8.x4.shared.b16 {%0,%1,%2,%3}, [%4];"
                    : "=r"(a[mt][0]), "=r"(a[mt][1]), "=r"(a[mt][2]), "=r"(a[mt][3])
                    : "r"(ad));
            }
            #pragma unroll
            for (int nt = 0; nt < 4; nt++) {
                uint32_t b0 = __float_as_uint(Bf[(k0 + tig) * BSTR + (nt << 3) + grp]);
                uint32_t b1 = __float_as_uint(Bf[(k0 + tig + 4) * BSTR + (nt << 3) + grp]);
                #pragma unroll
                for (int mt = 0; mt < 2; mt++) {
                    asm volatile(
                        "mma.sync.aligned.m16n8k8.row.col.f32.tf32.tf32.f32 "
                        "{%0,%1,%2,%3}, {%4,%5,%6,%7}, {%8,%9}, {%0,%1,%2,%3};"
                        : "+f"(tacc[mt][nt][0]), "+f"(tacc[mt][nt][1]),
                          "+f"(tacc[mt][nt][2]), "+f"(tacc[mt][nt][3])
                        : "r"(a[mt][0]), "r"(a[mt][1]), "r"(a[mt][2]), "r"(a[mt][3]),
                          "r"(b0), "r"(b1));
                }
            }
        }

        #pragma unroll
        for (int mt = 0; mt < 2; mt++)
            #pragma unroll
            for (int nt = 0; nt < 4; nt++) {
                acc[mt][nt][0] = fmaf(s[2 * mt],     tacc[mt][nt][0], acc[mt][nt][0]);
                acc[mt][nt][1] = fmaf(s[2 * mt],     tacc[mt][nt][1], acc[mt][nt][1]);
                acc[mt][nt][2] = fmaf(s[2 * mt + 1], tacc[mt][nt][2], acc[mt][nt][2]);
                acc[mt][nt][3] = fmaf(s[2 * mt + 1], tacc[mt][nt][3], acc[mt][nt][3]);
            }
        __syncthreads();   // all reads of bb done before it is refilled next iter
    }

    // write split-K partials [g][m][n]
    float* part = g_part + (size_t)g * (256 * 128);
    #pragma unroll
    for (int mt = 0; mt < 2; mt++) {
        int r0 = mbase + (mt << 4) + grp;
        #pragma unroll
        for (int nt = 0; nt < 4; nt++) {
            int col = (slice << 5) + (nt << 3) + (tig << 1);
            *(float2*)&part[r0 * 128 + col]       = make_float2(acc[mt][nt][0], acc[mt][nt][1]);
            *(float2*)&part[(r0 + 8) * 128 + col] = make_float2(acc[mt][nt][2], acc[mt][nt][3]);
        }
    }
}

// ---------------------------------------------------------------------------
__global__ void reduce_bias_relu(const float* __restrict__ b1) {
    int idx = blockIdx.x * 256 + threadIdx.x;   // 128 CTAs -> 32768
    float sum = b1[idx & 127];
    #pragma unroll
    for (int gg = 0; gg < GSPLIT; gg++) sum += g_part[(size_t)gg * 32768 + idx];
    g_h1[idx] = fmaxf(sum, 0.0f);
}

// ---------------------------------------------------------------------------
#define L23_BYTES ((16384 + 256 + 512 + 8) * 4)
__global__ void __launch_bounds__(256)
l2l3(const float* __restrict__ W2, const float* __restrict__ b2,
     const float* __restrict__ W3, const float* __restrict__ b3,
     float* __restrict__ out) {
    extern __shared__ float smf[];
    float* W2s  = smf;             // 16384
    float* rows = smf + 16384;     // [2][128]
    float* ps   = rows + 256;      // [kh][batch][128]
    float* red  = ps + 512;        // [8]
    const int t = threadIdx.x;
    const int b0 = blockIdx.x * 2, b1i = b0 + 1;

    {
        const float4* w4 = (const float4*)W2;
        float4* s4 = (float4*)W2s;
        #pragma unroll
        for (int i = t; i < 4096; i += 256) s4[i] = w4[i];
    }
    if (t < 128) rows[t] = g_h1[b0 * 128 + t];
    else         rows[t] = g_h1[b1i * 128 + (t - 128)];
    __syncthreads();

    const int kh = t >> 7, p = t & 127, k0 = kh << 6;
    float sA = 0.0f, sB = 0.0f;
    #pragma unroll
    for (int k = 0; k < 64; k++) {
        float wv = W2s[(k0 + k) * 128 + p];
        sA = fmaf(rows[k0 + k],       wv, sA);
        sB = fmaf(rows[128 + k0 + k], wv, sB);
    }
    ps[kh * 256 + p]       = sA;
    ps[kh * 256 + 128 + p] = sB;
    __syncthreads();

    const int bi = kh;
    float v = fmaxf(b2[p] + ps[bi * 128 + p] + ps[256 + bi * 128 + p], 0.0f) * W3[p];
    #pragma unroll
    for (int o = 16; o > 0; o >>= 1) v += __shfl_down_sync(0xffffffff, v, o);
    if ((t & 31) == 0) red[t >> 5] = v;
    __syncthreads();
    if (t == 0)   out[b0]  = red[0] + red[1] + red[2] + red[3] + b3[0];
    if (t == 128) out[b1i] = red[4] + red[5] + red[6] + red[7] + b3[0];
}

// ---------------------------------------------------------------------------
extern "C" void kernel_launch(void* const* d_in, const int* in_sizes, int n_in,
                              void* d_out, int out_size) {
    (void)in_sizes; (void)n_in; (void)out_size;
    const float* audio = (const float*)d_in[0];
    const float* video = (const float*)d_in[1];
    const float* text  = (const float*)d_in[2];
    const float* W1    = (const float*)d_in[3];
    const float* b1    = (const float*)d_in[4];
    const float* W2    = (const float*)d_in[5];
    const float* b2    = (const float*)d_in[6];
    const float* W3    = (const float*)d_in[7];
    const float* b3    = (const float*)d_in[8];
    float* out = (float*)d_out;

    cudaFuncSetAttribute(tfn_gemm, cudaFuncAttributeMaxDynamicSharedMemorySize,
                         SMEM_BYTES);
    cudaFuncSetAttribute(l2l3, cudaFuncAttributeMaxDynamicSharedMemorySize,
                         L23_BYTES);

    prep_T<<<256, 132>>>(text);
    dim3 grid(4, GSPLIT);
    tfn_gemm<<<grid, 256, SMEM_BYTES>>>(audio, video, W1);
    reduce_bias_relu<<<128, 256>>>(b1);
    l2l3<<<128, 256, L23_BYTES>>>(W2, b2, W3, b3, out);
}

// round 6
// speedup vs baseline: 1.3073x; 1.0266x over previous
#include <cuda_runtime.h>
#include <cstdint>

#define CHUNKS 1089
#define GSPLIT 38
#define TSTR   132
#define TSM_FLOATS (128*TSTR)            // 16896
#define BSTR   40
#define BROWS  129
#define BBUF_FLOATS (BROWS*BSTR)         // 5160
#define SMEM_BYTES ((TSM_FLOATS + 2*BBUF_FLOATS) * 4)   // 108864

__device__ float g_part[GSPLIT * 256 * 128];

__device__ __forceinline__ uint32_t smem_u32(const void* p) {
    uint32_t a;
    asm("{ .reg .u64 t; cvta.to.shared.u64 t, %1; cvt.u32.u64 %0, t; }" : "=r"(a) : "l"(p));
    return a;
}
__device__ __forceinline__ uint32_t f2tf32(float f) {
    uint32_t u; asm("cvt.rna.tf32.f32 %0, %1;" : "=r"(u) : "f"(f)); return u;
}
#define CP16(dst, src) asm volatile("cp.async.cg.shared.global [%0], [%1], 16;" :: "r"(dst), "l"(src))
#define CP_COMMIT()    asm volatile("cp.async.commit_group;")

// stage one W chunk slice: smem rows k=0..127 <- chunk rows 1..128; smem row 128 <- chunk row 0
__device__ __forceinline__ void stage_B(uint32_t dst, const float* W, int tid) {
    const char* src = (const char*)W;
    #pragma unroll
    for (int t = 0; t < 4; t++) {
        int task = tid + (t << 8);
        int k = task >> 3, j = task & 7;
        CP16(dst + (uint32_t)(k * BSTR + j * 4) * 4, src + (size_t)(k + 1) * 512 + j * 16);
    }
    if (tid < 8) CP16(dst + (uint32_t)(128 * BSTR) * 4 + (uint32_t)tid * 16, src + (size_t)tid * 16);
}

// ---------------------------------------------------------------------------
__global__ void __launch_bounds__(256, 2)
tfn_gemm(const float* __restrict__ audio, const float* __restrict__ video,
         const float* __restrict__ text, const float* __restrict__ W1) {
    extern __shared__ float sm[];
    float* Tsm = sm;
    float* B0  = sm + TSM_FLOATS;
    float* B1  = B0 + BBUF_FLOATS;

    const int tid   = threadIdx.x;
    const int m0    = blockIdx.x & 1;      // M half
    const int slice = blockIdx.x >> 1;     // 0..3 : 32-col N slice
    const int g     = blockIdx.y;          // 0..37 : chunk group

    const uint32_t sT  = smem_u32(Tsm);
    const uint32_t sB0 = smem_u32(B0);
    const uint32_t sB1 = smem_u32(B1);

    // stage T = raw text rows [m0*128, +128): 128 rows x 128 floats = 4096 x 16B
    {
        const char* src = (const char*)(text + (size_t)m0 * 128 * 128);
        #pragma unroll
        for (int t = 0; t < 16; t++) {
            int task = tid + (t << 8);
            int r = task >> 5, j = task & 31;
            CP16(sT + (uint32_t)(r * TSTR + j * 4) * 4, src + (size_t)r * 512 + j * 16);
        }
    }
    stage_B(sB0, W1 + (size_t)g * 16512 + slice * 32, tid);
    CP_COMMIT();

    const int warp = tid >> 5, lane = tid & 31;
    const int grp  = lane >> 2, tig = lane & 3;
    const int mbase = warp << 4;           // 16 rows per warp
    const uint32_t aBase = sT + (uint32_t)((mbase + (lane & 15)) * TSTR + ((lane >> 4) << 2)) * 4;

    float acc[4][4];
    #pragma unroll
    for (int nt = 0; nt < 4; nt++)
        #pragma unroll
        for (int e = 0; e < 4; e++) acc[nt][e] = 0.0f;

    const int nch = (CHUNKS - g + GSPLIT - 1) / GSPLIT;   // 28 or 29
    const int row0 = m0 * 128 + mbase + grp;

    for (int i = 0; i < nch; i++) {
        const int c = g + i * GSPLIT;

        if (i + 1 < nch) {
            stage_B((i & 1) ? sB0 : sB1,
                    W1 + (size_t)(c + GSPLIT) * 16512 + slice * 32, tid);
            CP_COMMIT();
            asm volatile("cp.async.wait_group 1;");
        } else {
            asm volatile("cp.async.wait_group 0;");
        }
        __syncthreads();

        if (i == 0) {   // one-time in-place RNA tf32 rounding of T (A operand)
            #pragma unroll
            for (int t = 0; t < 64; t++) {
                int idx = tid + (t << 8);
                int r = idx >> 7, cc = idx & 127;
                float* p = &Tsm[r * TSTR + cc];
                *p = __uint_as_float(f2tf32(*p));
            }
            __syncthreads();
        }

        const int ai = c / 33, vi = c - ai * 33;
        float s[2];
        #pragma unroll
        for (int r2 = 0; r2 < 2; r2++) {
            int row  = row0 + (r2 << 3);
            float av = (ai == 0) ? 1.0f : __ldg(&audio[row * 32 + ai - 1]);
            float vv = (vi == 0) ? 1.0f : __ldg(&video[row * 32 + vi - 1]);
            s[r2] = av * vv * 1.00048828125f;   // B-side tf32 truncation bias comp
        }

        float tacc[4][4];
        #pragma unroll
        for (int nt = 0; nt < 4; nt++)
            #pragma unroll
            for (int e = 0; e < 4; e++) tacc[nt][e] = 0.0f;

        const float* Bf = (i & 1) ? B1 : B0;
        #pragma unroll
        for (int kt = 0; kt < 16; kt++) {
            const int k0 = kt << 3;
            uint32_t a[4];
            asm volatile("ldmatrix.sync.aligned.m8n8.x4.shared.b16 {%0,%1,%2,%3}, [%4];"
                : "=r"(a[0]), "=r"(a[1]), "=r"(a[2]), "=r"(a[3])
                : "r"(aBase + (uint32_t)k0 * 4));
            #pragma unroll
            for (int nt = 0; nt < 4; nt++) {
                uint32_t b0 = __float_as_uint(Bf[(k0 + tig) * BSTR + (nt << 3) + grp]);
                uint32_t b1 = __float_as_uint(Bf[(k0 + tig + 4) * BSTR + (nt << 3) + grp]);
                asm volatile(
                    "mma.sync.aligned.m16n8k8.row.col.f32.tf32.tf32.f32 "
                    "{%0,%1,%2,%3}, {%4,%5,%6,%7}, {%8,%9}, {%0,%1,%2,%3};"
                    : "+f"(tacc[nt][0]), "+f"(tacc[nt][1]),
                      "+f"(tacc[nt][2]), "+f"(tacc[nt][3])
                    : "r"(a[0]), "r"(a[1]), "r"(a[2]), "r"(a[3]), "r"(b0), "r"(b1));
            }
        }

        // ones-column term (W chunk row 0, exact fp32) + scale fold
        #pragma unroll
        for (int nt = 0; nt < 4; nt++) {
            float2 w1c = *(const float2*)&Bf[128 * BSTR + (nt << 3) + (tig << 1)];
            acc[nt][0] = fmaf(s[0], tacc[nt][0] + w1c.x, acc[nt][0]);
            acc[nt][1] = fmaf(s[0], tacc[nt][1] + w1c.y, acc[nt][1]);
            acc[nt][2] = fmaf(s[1], tacc[nt][2] + w1c.x, acc[nt][2]);
            acc[nt][3] = fmaf(s[1], tacc[nt][3] + w1c.y, acc[nt][3]);
        }
        __syncthreads();
    }

    float* part = g_part + (size_t)g * 32768;
    #pragma unroll
    for (int nt = 0; nt < 4; nt++) {
        int col = (slice << 5) + (nt << 3) + (tig << 1);
        *(float2*)&part[row0 * 128 + col]       = make_float2(acc[nt][0], acc[nt][1]);
        *(float2*)&part[(row0 + 8) * 128 + col] = make_float2(acc[nt][2], acc[nt][3]);
    }
}

// ---------------------------------------------------------------------------
#define EPI_FLOATS (16384 + 768 + 512 + 8)
#define EPI_BYTES  (EPI_FLOATS * 4)
__global__ void __launch_bounds__(256)
epi(const float* __restrict__ b1, const float* __restrict__ W2,
    const float* __restrict__ b2, const float* __restrict__ W3,
    const float* __restrict__ b3, float* __restrict__ out) {
    extern __shared__ float smf[];
    float* W2s = smf;            // 16384
    float* h1t = smf + 16384;    // [k=128][r=4] stride 6
    float* h2s = h1t + 768;      // [4][128]
    float* red = h2s + 512;      // [8]
    const int t = threadIdx.x;
    const int bb0 = blockIdx.x * 4;

    {
        const char* src = (const char*)W2;
        const uint32_t dW = smem_u32(W2s);
        #pragma unroll
        for (int i = 0; i < 16; i++) {
            int task = t + (i << 8);
            CP16(dW + (uint32_t)task * 16, src + (size_t)task * 16);
        }
        CP_COMMIT();
    }

    const int p = t & 127, h = t >> 7;
    #pragma unroll
    for (int rr = 0; rr < 2; rr++) {
        int r = (rr << 1) + h;
        int row = bb0 + r;
        float sum = b1[p];
        #pragma unroll
        for (int gg = 0; gg < GSPLIT; gg++)
            sum += g_part[(size_t)gg * 32768 + row * 128 + p];
        h1t[p * 6 + r] = fmaxf(sum, 0.0f);
    }
    asm volatile("cp.async.wait_group 0;");
    __syncthreads();

    float sA = 0.0f, sB = 0.0f;
    #pragma unroll 8
    for (int k = 0; k < 128; k++) {
        float2 hv = *(const float2*)&h1t[k * 6 + (h << 1)];
        float wv = W2s[k * 128 + p];
        sA = fmaf(hv.x, wv, sA);
        sB = fmaf(hv.y, wv, sB);
    }
    float bv = b2[p];
    h2s[((h << 1) + 0) * 128 + p] = fmaxf(sA + bv, 0.0f);
    h2s[((h << 1) + 1) * 128 + p] = fmaxf(sB + bv, 0.0f);
    __syncthreads();

    const int w = t >> 5, lane = t & 31;
    const int r = w >> 1, seg = (w & 1) << 6;
    float v = h2s[r * 128 + seg + lane]      * W3[seg + lane]
            + h2s[r * 128 + seg + 32 + lane] * W3[seg + 32 + lane];
    #pragma unroll
    for (int o = 16; o > 0; o >>= 1) v += __shfl_down_sync(0xffffffff, v, o);
    if (lane == 0) red[w] = v;
    __syncthreads();
    if (t < 4) out[bb0 + t] = red[2 * t] + red[2 * t + 1] + b3[0];
}

// ---------------------------------------------------------------------------
extern "C" void kernel_launch(void* const* d_in, const int* in_sizes, int n_in,
                              void* d_out, int out_size) {
    (void)in_sizes; (void)n_in; (void)out_size;
    const float* audio = (const float*)d_in[0];
    const float* video = (const float*)d_in[1];
    const float* text  = (const float*)d_in[2];
    const float* W1    = (const float*)d_in[3];
    const float* b1    = (const float*)d_in[4];
    const float* W2    = (const float*)d_in[5];
    const float* b2    = (const float*)d_in[6];
    const float* W3    = (const float*)d_in[7];
    const float* b3    = (const float*)d_in[8];
    float* out = (float*)d_out;

    cudaFuncSetAttribute(tfn_gemm, cudaFuncAttributeMaxDynamicSharedMemorySize,
                         SMEM_BYTES);
    cudaFuncSetAttribute(epi, cudaFuncAttributeMaxDynamicSharedMemorySize,
                         EPI_BYTES);

    dim3 grid(8, GSPLIT);   // 304 CTAs = 2 per SM
    tfn_gemm<<<grid, 256, SMEM_BYTES>>>(audio, video, text, W1);
    epi<<<64, 256, EPI_BYTES>>>(b1, W2, b2, W3, b3, out);
}

// round 7
// speedup vs baseline: 1.9796x; 1.5142x over previous
#include <cuda_runtime.h>
#include <cuda_fp16.h>
#include <cstdint>

#define NCH 1089
#define NG  76
// smem layout (32-bit words)
#define THW      0                      // T fp16 [256 rows][68 words]
#define TH_WORDS (256*68)
#define STW      TH_WORDS               // W fp32 staging x2: [128 rows k][68 words]
#define ST_WORDS (128*68)
#define BHW      (STW + 2*ST_WORDS)     // W fp16 [64 n][68 words]
#define BH_WORDS (64*68)
#define ONW      (BHW + BH_WORDS)       // ones row fp32 x2 [64]
#define SMEM_WORDS (ONW + 128)
#define SMEM_BYTES (SMEM_WORDS*4)       // 157184

__device__ uint32_t g_Th[256 * 68];           // fp16x2 packed text (pad words zero)
__device__ float g_part[NG * 256 * 128];      // [g][m][n]

__device__ __forceinline__ uint32_t smem_u32(const void* p) {
    uint32_t a;
    asm("{ .reg .u64 t; cvta.to.shared.u64 t, %1; cvt.u32.u64 %0, t; }" : "=r"(a) : "l"(p));
    return a;
}
#define CP16(dst, src) asm volatile("cp.async.cg.shared.global [%0], [%1], 16;" :: "r"(dst), "l"(src))
#define CP_COMMIT()    asm volatile("cp.async.commit_group;")

// ---------------------------------------------------------------------------
__global__ void prep_Th(const float* __restrict__ text) {
    int m = blockIdx.x, t = threadIdx.x;      // 256 x 64
    float lo = text[m * 128 + 2 * t];
    float hi = text[m * 128 + 2 * t + 1];
    uint32_t d;
    asm("cvt.rn.f16x2.f32 %0, %1, %2;" : "=r"(d) : "f"(hi), "f"(lo));
    g_Th[m * 68 + t] = d;
}

// stage W chunk rows 1..128 (fp32, 64 cols) + row 0 into ones buffer
__device__ __forceinline__ void stage_chunk(uint32_t sb, int buf, const float* Wc, int tid) {
    const char* src = (const char*)Wc;
    uint32_t dst = sb + (STW + buf * ST_WORDS) * 4;
    #pragma unroll
    for (int t = 0; t < 8; t++) {
        int task = tid + (t << 8);
        int r = task >> 4, j = task & 15;
        CP16(dst + (uint32_t)(r * 68 + j * 4) * 4, src + (size_t)(r + 1) * 512 + j * 16);
    }
    if (tid < 16)
        CP16(sb + (ONW + buf * 64 + tid * 4) * 4, src + (size_t)tid * 16);
}

// ---------------------------------------------------------------------------
__global__ void __launch_bounds__(256, 1)
tfn_gemm(const float* __restrict__ audio, const float* __restrict__ video,
         const float* __restrict__ W1) {
    extern __shared__ uint32_t sw[];
    const uint32_t sb = smem_u32(sw);
    const int tid   = threadIdx.x;
    const int slice = blockIdx.x;            // 0/1 : 64-wide N slice
    const int g     = blockIdx.y;            // 0..75

    // prologue: stage T fp16 (4352 x 16B) + chunk 0, one commit group
    {
        const char* src = (const char*)g_Th;
        #pragma unroll
        for (int t = 0; t < 17; t++) {
            int task = tid + (t << 8);
            CP16(sb + (uint32_t)task * 16, src + (size_t)task * 16);
        }
    }
    stage_chunk(sb, 0, W1 + (size_t)g * 16512 + slice * 64, tid);
    CP_COMMIT();

    const int w = tid >> 5, lane = tid & 31;
    const int grp = lane >> 2, tg = lane & 3;
    const int mb = w << 5;                   // warp owns rows mb..mb+31
    const uint32_t aBase = sb + (uint32_t)((mb + (lane & 15)) * 68 + ((lane >> 4) << 2)) * 4;
    const int kp = tid & 15, ng = tid >> 4;  // cvt-pass mapping

    float acc[2][8][4];
    #pragma unroll
    for (int mt = 0; mt < 2; mt++)
        #pragma unroll
        for (int nt = 0; nt < 8; nt++)
            #pragma unroll
            for (int e = 0; e < 4; e++) acc[mt][nt][e] = 0.0f;

    const int nch = (NCH - g + NG - 1) / NG;   // 14 or 15
    const uint32_t bh = sb + BHW * 4;

    for (int i = 0; i < nch; i++) {
        const int c = g + i * NG;
        const int buf = i & 1;

        if (i + 1 < nch) {
            stage_chunk(sb, buf ^ 1, W1 + (size_t)(c + NG) * 16512 + slice * 64, tid);
            CP_COMMIT();
            asm volatile("cp.async.wait_group 1;");
        } else {
            asm volatile("cp.async.wait_group 0;");
        }
        __syncthreads();   // staging(i) visible; mma(i-1) reads of Bh done

        // ---- cvt pass: staging fp32 [k][n] -> Bh fp16 [n][k]
        {
            const uint32_t st = sb + (STW + buf * ST_WORDS) * 4;
            #pragma unroll
            for (int kb = 0; kb < 4; kb++) {
                int k = kb * 32 + 2 * kp;
                float r0x, r0y, r0z, r0w, r1x, r1y, r1z, r1w;
                asm("ld.shared.v4.f32 {%0,%1,%2,%3}, [%4];"
                    : "=f"(r0x), "=f"(r0y), "=f"(r0z), "=f"(r0w)
                    : "r"(st + (uint32_t)(k * 68 + ng * 4) * 4));
                asm("ld.shared.v4.f32 {%0,%1,%2,%3}, [%4];"
                    : "=f"(r1x), "=f"(r1y), "=f"(r1z), "=f"(r1w)
                    : "r"(st + (uint32_t)((k + 1) * 68 + ng * 4) * 4));
                uint32_t p0, p1, p2, p3;
                asm("cvt.rn.f16x2.f32 %0, %1, %2;" : "=r"(p0) : "f"(r1x), "f"(r0x));
                asm("cvt.rn.f16x2.f32 %0, %1, %2;" : "=r"(p1) : "f"(r1y), "f"(r0y));
                asm("cvt.rn.f16x2.f32 %0, %1, %2;" : "=r"(p2) : "f"(r1z), "f"(r0z));
                asm("cvt.rn.f16x2.f32 %0, %1, %2;" : "=r"(p3) : "f"(r1w), "f"(r0w));
                int wbase = kb * 16 + kp;
                asm volatile("st.shared.b32 [%0], %1;" :: "r"(bh + (uint32_t)((ng * 4 + 0) * 68 + wbase) * 4), "r"(p0) : "memory");
                asm volatile("st.shared.b32 [%0], %1;" :: "r"(bh + (uint32_t)((ng * 4 + 1) * 68 + wbase) * 4), "r"(p1) : "memory");
                asm volatile("st.shared.b32 [%0], %1;" :: "r"(bh + (uint32_t)((ng * 4 + 2) * 68 + wbase) * 4), "r"(p2) : "memory");
                asm volatile("st.shared.b32 [%0], %1;" :: "r"(bh + (uint32_t)((ng * 4 + 3) * 68 + wbase) * 4), "r"(p3) : "memory");
            }
        }
        __syncthreads();   // Bh(i) ready

        // ---- per-row scales
        const int ai = c / 33, vi = c - ai * 33;
        float s[4];
        #pragma unroll
        for (int q = 0; q < 4; q++) {
            int row = mb + grp + (q << 3);
            float av = (ai == 0) ? 1.0f : __ldg(&audio[row * 32 + ai - 1]);
            float vv = (vi == 0) ? 1.0f : __ldg(&video[row * 32 + vi - 1]);
            s[q] = av * vv;
        }

        // ---- fp16 k16 MMA: tacc = T @ Wc
        float tacc[2][8][4];
        #pragma unroll
        for (int mt = 0; mt < 2; mt++)
            #pragma unroll
            for (int nt = 0; nt < 8; nt++)
                #pragma unroll
                for (int e = 0; e < 4; e++) tacc[mt][nt][e] = 0.0f;

        #pragma unroll
        for (int kt = 0; kt < 8; kt++) {
            uint32_t a[2][4];
            #pragma unroll
            for (int mt = 0; mt < 2; mt++) {
                asm volatile("ldmatrix.sync.aligned.m8n8.x4.shared.b16 {%0,%1,%2,%3}, [%4];"
                    : "=r"(a[mt][0]), "=r"(a[mt][1]), "=r"(a[mt][2]), "=r"(a[mt][3])
                    : "r"(aBase + (uint32_t)(mt * 16 * 68 * 4 + kt * 32)));
            }
            uint32_t bfr[16];
            #pragma unroll
            for (int nt = 0; nt < 8; nt++) {
                uint32_t w0 = bh + (uint32_t)(((nt << 3) + grp) * 68 + (kt << 3) + tg) * 4;
                asm("ld.shared.b32 %0, [%1];" : "=r"(bfr[2 * nt])     : "r"(w0));
                asm("ld.shared.b32 %0, [%1];" : "=r"(bfr[2 * nt + 1]) : "r"(w0 + 16));
            }
            #pragma unroll
            for (int nt = 0; nt < 8; nt++)
                #pragma unroll
                for (int mt = 0; mt < 2; mt++) {
                    asm volatile(
                        "mma.sync.aligned.m16n8k16.row.col.f32.f16.f16.f32 "
                        "{%0,%1,%2,%3}, {%4,%5,%6,%7}, {%8,%9}, {%0,%1,%2,%3};"
                        : "+f"(tacc[mt][nt][0]), "+f"(tacc[mt][nt][1]),
                          "+f"(tacc[mt][nt][2]), "+f"(tacc[mt][nt][3])
                        : "r"(a[mt][0]), "r"(a[mt][1]), "r"(a[mt][2]), "r"(a[mt][3]),
                          "r"(bfr[2 * nt]), "r"(bfr[2 * nt + 1]));
                }
        }

        // ---- ones-column (W row 0, exact fp32) + scale fold
        const float* on = (const float*)sw + ONW + buf * 64;
        #pragma unroll
        for (int mt = 0; mt < 2; mt++)
            #pragma unroll
            for (int nt = 0; nt < 8; nt++) {
                float ox = on[(nt << 3) + (tg << 1)];
                float oy = on[(nt << 3) + (tg << 1) + 1];
                acc[mt][nt][0] = fmaf(s[2 * mt],     tacc[mt][nt][0] + ox, acc[mt][nt][0]);
                acc[mt][nt][1] = fmaf(s[2 * mt],     tacc[mt][nt][1] + oy, acc[mt][nt][1]);
                acc[mt][nt][2] = fmaf(s[2 * mt + 1], tacc[mt][nt][2] + ox, acc[mt][nt][2]);
                acc[mt][nt][3] = fmaf(s[2 * mt + 1], tacc[mt][nt][3] + oy, acc[mt][nt][3]);
            }
    }

    // ---- split-K partial store [g][m][n]
    float* part = g_part + (size_t)g * 32768;
    #pragma unroll
    for (int mt = 0; mt < 2; mt++) {
        int row = mb + (mt << 4) + grp;
        #pragma unroll
        for (int nt = 0; nt < 8; nt++) {
            int col = slice * 64 + (nt << 3) + (tg << 1);
            *(float2*)&part[row * 128 + col]       = make_float2(acc[mt][nt][0], acc[mt][nt][1]);
            *(float2*)&part[(row + 8) * 128 + col] = make_float2(acc[mt][nt][2], acc[mt][nt][3]);
        }
    }
}

// ---------------------------------------------------------------------------
#define EPI_FLOATS (16384 + 256 + 256 + 8)
#define EPI_BYTES  (EPI_FLOATS * 4)
__global__ void __launch_bounds__(256)
epi(const float* __restrict__ b1, const float* __restrict__ W2,
    const float* __restrict__ b2, const float* __restrict__ W3,
    const float* __restrict__ b3, float* __restrict__ out) {
    extern __shared__ float smf[];
    float* W2s = smf;            // 16384
    float* h1s = smf + 16384;    // [2][128]
    float* h2s = h1s + 256;      // [2][128]
    float* red = h2s + 256;      // [8]
    const int t = threadIdx.x;
    const int r0 = blockIdx.x * 2;

    {
        const char* src = (const char*)W2;
        const uint32_t dW = smem_u32(W2s);
        #pragma unroll
        for (int i = 0; i < 16; i++) {
            int task = t + (i << 8);
            CP16(dW + (uint32_t)task * 16, src + (size_t)task * 16);
        }
        CP_COMMIT();
    }

    const int p = t & 127, h = t >> 7;
    {
        int row = r0 + h;
        float sum = b1[p];
        #pragma unroll 4
        for (int gg = 0; gg < NG; gg++)
            sum += g_part[(size_t)gg * 32768 + row * 128 + p];
        h1s[h * 128 + p] = fmaxf(sum, 0.0f);
    }
    asm volatile("cp.async.wait_group 0;");
    __syncthreads();

    float sA = 0.0f;
    #pragma unroll 8
    for (int k = 0; k < 128; k++)
        sA = fmaf(h1s[h * 128 + k], W2s[k * 128 + p], sA);
    h2s[h * 128 + p] = fmaxf(sA + b2[p], 0.0f);
    __syncthreads();

    const int w = t >> 5, lane = t & 31;
    float v = h2s[(w >> 2) * 128 + ((w & 3) << 5) + lane] * W3[((w & 3) << 5) + lane];
    #pragma unroll
    for (int o = 16; o > 0; o >>= 1) v += __shfl_down_sync(0xffffffff, v, o);
    if (lane == 0) red[w] = v;
    __syncthreads();
    if (t < 2) out[r0 + t] = red[t * 4] + red[t * 4 + 1] + red[t * 4 + 2] + red[t * 4 + 3] + b3[0];
}

// ---------------------------------------------------------------------------
extern "C" void kernel_launch(void* const* d_in, const int* in_sizes, int n_in,
                              void* d_out, int out_size) {
    (void)in_sizes; (void)n_in; (void)out_size;
    const float* audio = (const float*)d_in[0];
    const float* video = (const float*)d_in[1];
    const float* text  = (const float*)d_in[2];
    const float* W1    = (const float*)d_in[3];
    const float* b1    = (const float*)d_in[4];
    const float* W2    = (const float*)d_in[5];
    const float* b2    = (const float*)d_in[6];
    const float* W3    = (const float*)d_in[7];
    const float* b3    = (const float*)d_in[8];
    float* out = (float*)d_out;

    cudaFuncSetAttribute(tfn_gemm, cudaFuncAttributeMaxDynamicSharedMemorySize,
                         SMEM_BYTES);
    cudaFuncSetAttribute(epi, cudaFuncAttributeMaxDynamicSharedMemorySize,
                         EPI_BYTES);

    prep_Th<<<256, 64>>>(text);
    dim3 grid(2, NG);   // 152 CTAs = one wave
    tfn_gemm<<<grid, 256, SMEM_BYTES>>>(audio, video, W1);
    epi<<<128, 256, EPI_BYTES>>>(b1, W2, b2, W3, b3, out);
}

// round 8
// speedup vs baseline: 2.0679x; 1.0446x over previous
#include <cuda_runtime.h>
#include <cuda_fp16.h>
#include <cstdint>

#define NCH 1089
#define NG  76
#define TSTRW 68
#define T_WORDS (256*TSTRW)
#define BSTRW 36
#define B_WORDS (128*BSTRW)
#define BW  T_WORDS
#define OW  (BW + 2*B_WORDS)
#define SMEM_WORDS (OW + 128)
#define SMEM_BYTES (SMEM_WORDS*4)

__device__ float g_part[NG * 256 * 128];   // [g][m][n]

__device__ __forceinline__ uint32_t smem_u32(const void* p) {
    uint32_t a;
    asm("{ .reg .u64 t; cvta.to.shared.u64 t, %1; cvt.u32.u64 %0, t; }" : "=r"(a) : "l"(p));
    return a;
}
#define CP16(dst, src) asm volatile("cp.async.cg.shared.global [%0], [%1], 16;" :: "r"(dst), "l"(src))
#define CP_COMMIT()    asm volatile("cp.async.commit_group;")

// ---------------------------------------------------------------------------
__global__ void __launch_bounds__(512, 1)
tfn_gemm(const float* __restrict__ audio, const float* __restrict__ video,
         const float* __restrict__ text, const float* __restrict__ W1) {
    extern __shared__ uint32_t sw[];
    const uint32_t sb = smem_u32(sw);
    const int tid = threadIdx.x;
    const int w = tid >> 5, lane = tid & 31;
    const int grp = lane >> 2, tg = lane & 3;
    const int slice = blockIdx.x;            // 0/1 : 64-col N slice
    const int g     = blockIdx.y;            // 0..75 : chunk group

    const int kr = tid >> 4, c4 = tid & 15;

    // prefetch W chunk 0 into registers (chunk rows 1..128 + ones row 0)
    float4 wv[4]; float4 ov = make_float4(0.f, 0.f, 0.f, 0.f);
    {
        const float* Wc = W1 + (size_t)g * 16512 + slice * 64;
        #pragma unroll
        for (int t = 0; t < 4; t++)
            wv[t] = __ldg((const float4*)(Wc + (size_t)(kr + 32 * t + 1) * 128 + c4 * 4));
        if (tid < 16) ov = __ldg((const float4*)(Wc + tid * 4));
    }

    // build T fp16 in smem once
    {
        const float* src = text + (size_t)(tid >> 1) * 128 + (tid & 1) * 64;
        uint32_t dst = sb + (uint32_t)((tid >> 1) * TSTRW + (tid & 1) * 32) * 4;
        #pragma unroll
        for (int j = 0; j < 16; j++) {
            float4 v = __ldg((const float4*)(src + j * 4));
            uint32_t p0, p1;
            asm("cvt.rn.f16x2.f32 %0, %1, %2;" : "=r"(p0) : "f"(v.y), "f"(v.x));
            asm("cvt.rn.f16x2.f32 %0, %1, %2;" : "=r"(p1) : "f"(v.w), "f"(v.z));
            asm volatile("st.shared.v2.b32 [%0], {%1,%2};"
                :: "r"(dst + j * 8), "r"(p0), "r"(p1) : "memory");
        }
    }

    const int nch = (NCH - g + NG - 1) / NG;   // 14 or 15
    const uint32_t bh0 = sb + BW * 4;
    const int row0 = (w << 4) + grp;
    const uint32_t aAddr = sb + (uint32_t)((w * 16 + (lane & 15)) * TSTRW) * 4
                         + ((uint32_t)(lane >> 4) << 4);

    float acc[8][4];
    #pragma unroll
    for (int nt = 0; nt < 8; nt++)
        #pragma unroll
        for (int e = 0; e < 4; e++) acc[nt][e] = 0.0f;

    for (int i = 0; i < nch; i++) {
        const int cc = g + i * NG;
        const int buf = i & 1;

        // store W regs -> Bh[buf] fp16 [k][n]; ones -> fp32
        {
            const uint32_t bb = bh0 + (uint32_t)buf * (B_WORDS * 4);
            #pragma unroll
            for (int t = 0; t < 4; t++) {
                uint32_t p0, p1;
                asm("cvt.rn.f16x2.f32 %0, %1, %2;" : "=r"(p0) : "f"(wv[t].y), "f"(wv[t].x));
                asm("cvt.rn.f16x2.f32 %0, %1, %2;" : "=r"(p1) : "f"(wv[t].w), "f"(wv[t].z));
                asm volatile("st.shared.v2.b32 [%0], {%1,%2};"
                    :: "r"(bb + (uint32_t)((kr + 32 * t) * BSTRW + 2 * c4) * 4),
                       "r"(p0), "r"(p1) : "memory");
            }
            if (tid < 16)
                asm volatile("st.shared.v4.f32 [%0], {%1,%2,%3,%4};"
                    :: "r"(sb + (uint32_t)(OW + buf * 64 + tid * 4) * 4),
                       "f"(ov.x), "f"(ov.y), "f"(ov.z), "f"(ov.w) : "memory");
        }
        __syncthreads();

        // prefetch next chunk into regs
        if (i + 1 < nch) {
            const float* Wn = W1 + (size_t)(cc + NG) * 16512 + slice * 64;
            #pragma unroll
            for (int t = 0; t < 4; t++)
                wv[t] = __ldg((const float4*)(Wn + (size_t)(kr + 32 * t + 1) * 128 + c4 * 4));
            if (tid < 16) ov = __ldg((const float4*)(Wn + tid * 4));
        }

        // per-row scales
        const int ai = cc / 33, vi = cc - ai * 33;
        float s0, s1;
        {
            float av0 = (ai == 0) ? 1.0f : __ldg(&audio[row0 * 32 + ai - 1]);
            float vv0 = (vi == 0) ? 1.0f : __ldg(&video[row0 * 32 + vi - 1]);
            float av1 = (ai == 0) ? 1.0f : __ldg(&audio[(row0 + 8) * 32 + ai - 1]);
            float vv1 = (vi == 0) ? 1.0f : __ldg(&video[(row0 + 8) * 32 + vi - 1]);
            s0 = av0 * vv0; s1 = av1 * vv1;
        }

        float tacc[8][4];
        #pragma unroll
        for (int nt = 0; nt < 8; nt++)
            #pragma unroll
            for (int e = 0; e < 4; e++) tacc[nt][e] = 0.0f;

        const uint32_t bb = bh0 + (uint32_t)buf * (B_WORDS * 4);
        #pragma unroll
        for (int kt = 0; kt < 8; kt++) {
            uint32_t a0, a1, a2, a3;
            asm volatile("ldmatrix.sync.aligned.m8n8.x4.shared.b16 {%0,%1,%2,%3}, [%4];"
                : "=r"(a0), "=r"(a1), "=r"(a2), "=r"(a3)
                : "r"(aAddr + (uint32_t)kt * 32));
            const uint32_t bRow = bb + (uint32_t)((kt * 16 + (lane & 15)) * BSTRW) * 4
                                + ((uint32_t)(lane >> 4) << 4);
            #pragma unroll
            for (int np = 0; np < 4; np++) {
                uint32_t r0, r1, r2, r3;
                asm volatile("ldmatrix.sync.aligned.m8n8.x4.trans.shared.b16 {%0,%1,%2,%3}, [%4];"
                    : "=r"(r0), "=r"(r1), "=r"(r2), "=r"(r3)
                    : "r"(bRow + (uint32_t)np * 32));
                asm volatile(
                    "mma.sync.aligned.m16n8k16.row.col.f32.f16.f16.f32 "
                    "{%0,%1,%2,%3}, {%4,%5,%6,%7}, {%8,%9}, {%0,%1,%2,%3};"
                    : "+f"(tacc[2 * np][0]), "+f"(tacc[2 * np][1]),
                      "+f"(tacc[2 * np][2]), "+f"(tacc[2 * np][3])
                    : "r"(a0), "r"(a1), "r"(a2), "r"(a3), "r"(r0), "r"(r1));
                asm volatile(
                    "mma.sync.aligned.m16n8k16.row.col.f32.f16.f16.f32 "
                    "{%0,%1,%2,%3}, {%4,%5,%6,%7}, {%8,%9}, {%0,%1,%2,%3};"
                    : "+f"(tacc[2 * np + 1][0]), "+f"(tacc[2 * np + 1][1]),
                      "+f"(tacc[2 * np + 1][2]), "+f"(tacc[2 * np + 1][3])
                    : "r"(a0), "r"(a1), "r"(a2), "r"(a3), "r"(r2), "r"(r3));
            }
        }

        // ones-column (exact fp32) + scale fold
        const float* on = (const float*)sw + OW + buf * 64;
        #pragma unroll
        for (int nt = 0; nt < 8; nt++) {
            float ox = on[nt * 8 + 2 * tg];
            float oy = on[nt * 8 + 2 * tg + 1];
            acc[nt][0] = fmaf(s0, tacc[nt][0] + ox, acc[nt][0]);
            acc[nt][1] = fmaf(s0, tacc[nt][1] + oy, acc[nt][1]);
            acc[nt][2] = fmaf(s1, tacc[nt][2] + ox, acc[nt][2]);
            acc[nt][3] = fmaf(s1, tacc[nt][3] + oy, acc[nt][3]);
        }
    }

    float* part = g_part + (size_t)g * 32768;
    #pragma unroll
    for (int nt = 0; nt < 8; nt++) {
        int col = slice * 64 + nt * 8 + 2 * tg;
        *(float2*)&part[row0 * 128 + col]       = make_float2(acc[nt][0], acc[nt][1]);
        *(float2*)&part[(row0 + 8) * 128 + col] = make_float2(acc[nt][2], acc[nt][3]);
    }
}

// ---------------------------------------------------------------------------
#define EPI_FLOATS (16384 + 512 + 256 + 256 + 8)
#define EPI_BYTES  (EPI_FLOATS * 4)
__global__ void __launch_bounds__(256)
epi(const float* __restrict__ b1, const float* __restrict__ W2,
    const float* __restrict__ b2, const float* __restrict__ W3,
    const float* __restrict__ b3, float* __restrict__ out) {
    extern __shared__ float smf[];
    float* W2s = smf;            // 16384
    float* ps  = smf + 16384;    // [2 rows][2 halves][128]
    float* h1s = ps + 512;       // [2][128]
    float* h2s = h1s + 256;      // [2][128]
    float* red = h2s + 256;      // [8]
    const int t = threadIdx.x;
    const int r0 = blockIdx.x * 2;

    {
        const char* src = (const char*)W2;
        const uint32_t dW = smem_u32(W2s);
        #pragma unroll
        for (int i = 0; i < 16; i++) {
            int task = t + (i << 8);
            CP16(dW + (uint32_t)task * 16, src + (size_t)task * 16);
        }
        CP_COMMIT();
    }

    const int p = t & 127, h = t >> 7;
    #pragma unroll
    for (int rr = 0; rr < 2; rr++) {
        int row = r0 + rr;
        float sum = 0.0f;
        #pragma unroll
        for (int gg2 = 0; gg2 < 38; gg2++)
            sum += g_part[(size_t)(2 * gg2 + h) * 32768 + row * 128 + p];
        ps[(rr * 2 + h) * 128 + p] = sum;
    }
    asm volatile("cp.async.wait_group 0;");
    __syncthreads();

    h1s[h * 128 + p] = fmaxf(ps[(h * 2 + 0) * 128 + p] + ps[(h * 2 + 1) * 128 + p]
                             + b1[p], 0.0f);
    __syncthreads();

    float sA = 0.0f;
    #pragma unroll 8
    for (int k = 0; k < 128; k++)
        sA = fmaf(h1s[h * 128 + k], W2s[k * 128 + p], sA);
    h2s[h * 128 + p] = fmaxf(sA + b2[p], 0.0f);
    __syncthreads();

    const int w = t >> 5, lane = t & 31;
    float v = h2s[(w >> 2) * 128 + ((w & 3) << 5) + lane] * W3[((w & 3) << 5) + lane];
    #pragma unroll
    for (int o = 16; o > 0; o >>= 1) v += __shfl_down_sync(0xffffffff, v, o);
    if (lane == 0) red[w] = v;
    __syncthreads();
    if (t < 2) out[r0 + t] = red[t * 4] + red[t * 4 + 1] + red[t * 4 + 2]
                           + red[t * 4 + 3] + b3[0];
}

// ---------------------------------------------------------------------------
extern "C" void kernel_launch(void* const* d_in, const int* in_sizes, int n_in,
                              void* d_out, int out_size) {
    (void)in_sizes; (void)n_in; (void)out_size;
    const float* audio = (const float*)d_in[0];
    const float* video = (const float*)d_in[1];
    const float* text  = (const float*)d_in[2];
    const float* W1    = (const float*)d_in[3];
    const float* b1    = (const float*)d_in[4];
    const float* W2    = (const float*)d_in[5];
    const float* b2    = (const float*)d_in[6];
    const float* W3    = (const float*)d_in[7];
    const float* b3    = (const float*)d_in[8];
    float* out = (float*)d_out;

    cudaFuncSetAttribute(tfn_gemm, cudaFuncAttributeMaxDynamicSharedMemorySize,
                         SMEM_BYTES);
    cudaFuncSetAttribute(epi, cudaFuncAttributeMaxDynamicSharedMemorySize,
                         EPI_BYTES);

    dim3 grid(2, NG);   // 152 CTAs = one wave
    tfn_gemm<<<grid, 512, SMEM_BYTES>>>(audio, video, text, W1);
    epi<<<128, 256, EPI_BYTES>>>(b1, W2, b2, W3, b3, out);
}

// round 9
// speedup vs baseline: 2.0746x; 1.0032x over previous
#include <cuda_runtime.h>
#include <cuda_fp16.h>
#include <cstdint>

#define NCH 1089
#define NG  76
#define TSTRW 68
#define T_WORDS (256*TSTRW)
#define BSTRW 36
#define B_WORDS (128*BSTRW)
#define BW  T_WORDS
#define OW  (BW + 2*B_WORDS)
#define SMEM_WORDS (OW + 128)
#define SMEM_BYTES (SMEM_WORDS*4)

__device__ float g_part[NG * 256 * 128];   // [g][m][n]

__device__ __forceinline__ uint32_t smem_u32(const void* p) {
    uint32_t a;
    asm("{ .reg .u64 t; cvta.to.shared.u64 t, %1; cvt.u32.u64 %0, t; }" : "=r"(a) : "l"(p));
    return a;
}
#define CP16(dst, src) asm volatile("cp.async.cg.shared.global [%0], [%1], 16;" :: "r"(dst), "l"(src))
#define CP_COMMIT()    asm volatile("cp.async.commit_group;")

// ---------------------------------------------------------------------------
__global__ void __launch_bounds__(512, 1)
tfn_gemm(const float* __restrict__ audio, const float* __restrict__ video,
         const float* __restrict__ text, const float* __restrict__ W1) {
    extern __shared__ uint32_t sw[];
    const uint32_t sb = smem_u32(sw);
    const int tid = threadIdx.x;
    const int w = tid >> 5, lane = tid & 31;
    const int grp = lane >> 2, tg = lane & 3;
    const int slice = blockIdx.x;            // 0/1 : 64-col N slice
    const int g     = blockIdx.y;            // 0..75 : chunk group

    const int kr = tid >> 4, c4 = tid & 15;
    const uint32_t bh0 = sb + BW * 4;

    // ---- LDG chunk 0 -> regs
    float4 wv[4]; float4 ov = make_float4(0.f, 0.f, 0.f, 0.f);
    {
        const float* Wc = W1 + (size_t)g * 16512 + slice * 64;
        #pragma unroll
        for (int t = 0; t < 4; t++)
            wv[t] = __ldg((const float4*)(Wc + (size_t)(kr + 32 * t + 1) * 128 + c4 * 4));
        if (tid < 16) ov = __ldg((const float4*)(Wc + tid * 4));
    }

    // ---- build T fp16 in smem once
    {
        const float* src = text + (size_t)(tid >> 1) * 128 + (tid & 1) * 64;
        uint32_t dst = sb + (uint32_t)((tid >> 1) * TSTRW + (tid & 1) * 32) * 4;
        #pragma unroll
        for (int j = 0; j < 16; j++) {
            float4 v = __ldg((const float4*)(src + j * 4));
            uint32_t p0, p1;
            asm("cvt.rn.f16x2.f32 %0, %1, %2;" : "=r"(p0) : "f"(v.y), "f"(v.x));
            asm("cvt.rn.f16x2.f32 %0, %1, %2;" : "=r"(p1) : "f"(v.w), "f"(v.z));
            asm volatile("st.shared.v2.b32 [%0], {%1,%2};"
                :: "r"(dst + j * 8), "r"(p0), "r"(p1) : "memory");
        }
    }

    // ---- STS chunk 0 -> buf 0 (exposed once)
    {
        #pragma unroll
        for (int t = 0; t < 4; t++) {
            uint32_t p0, p1;
            asm("cvt.rn.f16x2.f32 %0, %1, %2;" : "=r"(p0) : "f"(wv[t].y), "f"(wv[t].x));
            asm("cvt.rn.f16x2.f32 %0, %1, %2;" : "=r"(p1) : "f"(wv[t].w), "f"(wv[t].z));
            asm volatile("st.shared.v2.b32 [%0], {%1,%2};"
                :: "r"(bh0 + (uint32_t)((kr + 32 * t) * BSTRW + 2 * c4) * 4),
                   "r"(p0), "r"(p1) : "memory");
        }
        if (tid < 16)
            asm volatile("st.shared.v4.f32 [%0], {%1,%2,%3,%4};"
                :: "r"(sb + (uint32_t)(OW + tid * 4) * 4),
                   "f"(ov.x), "f"(ov.y), "f"(ov.z), "f"(ov.w) : "memory");
    }
    __syncthreads();

    const int nch = (NCH - g + NG - 1) / NG;   // 14 or 15

    // ---- LDG chunk 1 -> regs
    if (nch > 1) {
        const float* Wn = W1 + (size_t)(g + NG) * 16512 + slice * 64;
        #pragma unroll
        for (int t = 0; t < 4; t++)
            wv[t] = __ldg((const float4*)(Wn + (size_t)(kr + 32 * t + 1) * 128 + c4 * 4));
        if (tid < 16) ov = __ldg((const float4*)(Wn + tid * 4));
    }

    const int row0 = (w << 4) + grp;
    const uint32_t aAddr = sb + (uint32_t)((w * 16 + (lane & 15)) * TSTRW) * 4
                         + ((uint32_t)(lane >> 4) << 4);

    float acc[8][4];
    #pragma unroll
    for (int nt = 0; nt < 8; nt++)
        #pragma unroll
        for (int e = 0; e < 4; e++) acc[nt][e] = 0.0f;

    for (int i = 0; i < nch; i++) {
        const int cc = g + i * NG;
        const int buf = i & 1;

        // ---- STS chunk i+1 -> buf^1 (hidden under MMA(i) below)
        if (i + 1 < nch) {
            const uint32_t bn = bh0 + (uint32_t)(buf ^ 1) * (B_WORDS * 4);
            #pragma unroll
            for (int t = 0; t < 4; t++) {
                uint32_t p0, p1;
                asm("cvt.rn.f16x2.f32 %0, %1, %2;" : "=r"(p0) : "f"(wv[t].y), "f"(wv[t].x));
                asm("cvt.rn.f16x2.f32 %0, %1, %2;" : "=r"(p1) : "f"(wv[t].w), "f"(wv[t].z));
                asm volatile("st.shared.v2.b32 [%0], {%1,%2};"
                    :: "r"(bn + (uint32_t)((kr + 32 * t) * BSTRW + 2 * c4) * 4),
                       "r"(p0), "r"(p1) : "memory");
            }
            if (tid < 16)
                asm volatile("st.shared.v4.f32 [%0], {%1,%2,%3,%4};"
                    :: "r"(sb + (uint32_t)(OW + (buf ^ 1) * 64 + tid * 4) * 4),
                       "f"(ov.x), "f"(ov.y), "f"(ov.z), "f"(ov.w) : "memory");
        }
        // ---- LDG chunk i+2 -> regs (hidden)
        if (i + 2 < nch) {
            const float* Wn = W1 + (size_t)(cc + 2 * NG) * 16512 + slice * 64;
            #pragma unroll
            for (int t = 0; t < 4; t++)
                wv[t] = __ldg((const float4*)(Wn + (size_t)(kr + 32 * t + 1) * 128 + c4 * 4));
            if (tid < 16) ov = __ldg((const float4*)(Wn + tid * 4));
        }

        // ---- per-row scales for chunk i
        const int ai = cc / 33, vi = cc - ai * 33;
        float s0, s1;
        {
            float av0 = (ai == 0) ? 1.0f : __ldg(&audio[row0 * 32 + ai - 1]);
            float vv0 = (vi == 0) ? 1.0f : __ldg(&video[row0 * 32 + vi - 1]);
            float av1 = (ai == 0) ? 1.0f : __ldg(&audio[(row0 + 8) * 32 + ai - 1]);
            float vv1 = (vi == 0) ? 1.0f : __ldg(&video[(row0 + 8) * 32 + vi - 1]);
            s0 = av0 * vv0; s1 = av1 * vv1;
        }

        // ---- MMA on buf(i)
        float tacc[8][4];
        #pragma unroll
        for (int nt = 0; nt < 8; nt++)
            #pragma unroll
            for (int e = 0; e < 4; e++) tacc[nt][e] = 0.0f;

        const uint32_t bb = bh0 + (uint32_t)buf * (B_WORDS * 4);
        #pragma unroll
        for (int kt = 0; kt < 8; kt++) {
            uint32_t a0, a1, a2, a3;
            asm volatile("ldmatrix.sync.aligned.m8n8.x4.shared.b16 {%0,%1,%2,%3}, [%4];"
                : "=r"(a0), "=r"(a1), "=r"(a2), "=r"(a3)
                : "r"(aAddr + (uint32_t)kt * 32));
            const uint32_t bRow = bb + (uint32_t)((kt * 16 + (lane & 15)) * BSTRW) * 4
                                + ((uint32_t)(lane >> 4) << 4);
            #pragma unroll
            for (int np = 0; np < 4; np++) {
                uint32_t r0, r1, r2, r3;
                asm volatile("ldmatrix.sync.aligned.m8n8.x4.trans.shared.b16 {%0,%1,%2,%3}, [%4];"
                    : "=r"(r0), "=r"(r1), "=r"(r2), "=r"(r3)
                    : "r"(bRow + (uint32_t)np * 32));
                asm volatile(
                    "mma.sync.aligned.m16n8k16.row.col.f32.f16.f16.f32 "
                    "{%0,%1,%2,%3}, {%4,%5,%6,%7}, {%8,%9}, {%0,%1,%2,%3};"
                    : "+f"(tacc[2 * np][0]), "+f"(tacc[2 * np][1]),
                      "+f"(tacc[2 * np][2]), "+f"(tacc[2 * np][3])
                    : "r"(a0), "r"(a1), "r"(a2), "r"(a3), "r"(r0), "r"(r1));
                asm volatile(
                    "mma.sync.aligned.m16n8k16.row.col.f32.f16.f16.f32 "
                    "{%0,%1,%2,%3}, {%4,%5,%6,%7}, {%8,%9}, {%0,%1,%2,%3};"
                    : "+f"(tacc[2 * np + 1][0]), "+f"(tacc[2 * np + 1][1]),
                      "+f"(tacc[2 * np + 1][2]), "+f"(tacc[2 * np + 1][3])
                    : "r"(a0), "r"(a1), "r"(a2), "r"(a3), "r"(r2), "r"(r3));
            }
        }

        // ---- ones-column (exact fp32) + scale fold
        const float* on = (const float*)sw + OW + buf * 64;
        #pragma unroll
        for (int nt = 0; nt < 8; nt++) {
            float ox = on[nt * 8 + 2 * tg];
            float oy = on[nt * 8 + 2 * tg + 1];
            acc[nt][0] = fmaf(s0, tacc[nt][0] + ox, acc[nt][0]);
            acc[nt][1] = fmaf(s0, tacc[nt][1] + oy, acc[nt][1]);
            acc[nt][2] = fmaf(s1, tacc[nt][2] + ox, acc[nt][2]);
            acc[nt][3] = fmaf(s1, tacc[nt][3] + oy, acc[nt][3]);
        }
        __syncthreads();
    }

    float* part = g_part + (size_t)g * 32768;
    #pragma unroll
    for (int nt = 0; nt < 8; nt++) {
        int col = slice * 64 + nt * 8 + 2 * tg;
        *(float2*)&part[row0 * 128 + col]       = make_float2(acc[nt][0], acc[nt][1]);
        *(float2*)&part[(row0 + 8) * 128 + col] = make_float2(acc[nt][2], acc[nt][3]);
    }
}

// ---------------------------------------------------------------------------
// epi v2: one batch row per CTA; float4 split-K reduce + L1 bias/relu + L2 + L3
#define EPI_FLOATS (16384 + 1024 + 128 + 256 + 4)
#define EPI_BYTES  (EPI_FLOATS * 4)
__global__ void __launch_bounds__(256)
epi(const float* __restrict__ b1, const float* __restrict__ W2,
    const float* __restrict__ b2, const float* __restrict__ W3,
    const float* __restrict__ b3, float* __restrict__ out) {
    extern __shared__ float smf[];
    float* W2s  = smf;            // 16384
    float* ps   = smf + 16384;    // [8 buckets][128]
    float* h1s  = ps + 1024;      // [128]
    float* psum = h1s + 128;      // [2][128]
    float* red  = psum + 256;     // [4]
    const int t = threadIdx.x;
    const int row = blockIdx.x;

    {   // stage W2 (overlaps the reduce)
        const char* src = (const char*)W2;
        const uint32_t dW = smem_u32(W2s);
        #pragma unroll
        for (int i = 0; i < 16; i++) {
            int task = t + (i << 8);
            CP16(dW + (uint32_t)task * 16, src + (size_t)task * 16);
        }
        CP_COMMIT();
    }

    // split-K reduce: bucket s sums groups {s, s+8, ...}, float4-wide
    {
        const int q = t & 31, s = t >> 5;
        float4 sum = make_float4(0.f, 0.f, 0.f, 0.f);
        const float* base = g_part + (size_t)row * 128 + q * 4;
        #pragma unroll 10
        for (int gg = s; gg < NG; gg += 8) {
            float4 v = __ldg((const float4*)(base + (size_t)gg * 32768));
            sum.x += v.x; sum.y += v.y; sum.z += v.z; sum.w += v.w;
        }
        *(float4*)&ps[s * 128 + q * 4] = sum;
    }
    asm volatile("cp.async.wait_group 0;");
    __syncthreads();

    if (t < 128) {
        float sum = b1[t];
        #pragma unroll
        for (int s = 0; s < 8; s++) sum += ps[s * 128 + t];
        h1s[t] = fmaxf(sum, 0.0f);
    }
    __syncthreads();

    // L2: p = t&127, k-half = t>>7
    {
        const int p = t & 127, kh = t >> 7, k0 = kh << 6;
        float a = 0.0f;
        #pragma unroll 8
        for (int k = 0; k < 64; k++)
            a = fmaf(h1s[k0 + k], W2s[(k0 + k) * 128 + p], a);
        psum[kh * 128 + p] = a;
    }
    __syncthreads();

    // L3
    if (t < 128) {
        float h2 = fmaxf(psum[t] + psum[128 + t] + b2[t], 0.0f) * __ldg(&W3[t]);
        #pragma unroll
        for (int o = 16; o > 0; o >>= 1) h2 += __shfl_down_sync(0xffffffff, h2, o);
        if ((t & 31) == 0) red[t >> 5] = h2;
    }
    __syncthreads();
    if (t == 0) out[row] = red[0] + red[1] + red[2] + red[3] + b3[0];
}

// ---------------------------------------------------------------------------
extern "C" void kernel_launch(void* const* d_in, const int* in_sizes, int n_in,
                              void* d_out, int out_size) {
    (void)in_sizes; (void)n_in; (void)out_size;
    const float* audio = (const float*)d_in[0];
    const float* video = (const float*)d_in[1];
    const float* text  = (const float*)d_in[2];
    const float* W1    = (const float*)d_in[3];
    const float* b1    = (const float*)d_in[4];
    const float* W2    = (const float*)d_in[5];
    const float* b2    = (const float*)d_in[6];
    const float* W3    = (const float*)d_in[7];
    const float* b3    = (const float*)d_in[8];
    float* out = (float*)d_out;

    cudaFuncSetAttribute(tfn_gemm, cudaFuncAttributeMaxDynamicSharedMemorySize,
                         SMEM_BYTES);
    cudaFuncSetAttribute(epi, cudaFuncAttributeMaxDynamicSharedMemorySize,
                         EPI_BYTES);

    dim3 grid(2, NG);   // 152 CTAs = one wave
    tfn_gemm<<<grid, 512, SMEM_BYTES>>>(audio, video, text, W1);
    epi<<<256, 256, EPI_BYTES>>>(b1, W2, b2, W3, b3, out);
}